// round 7
// baseline (speedup 1.0000x reference)
#include <cuda_runtime.h>

// DepthWiseConv1d: inputs [B=32, C=128, L=8192] fp32, weight [C,3], bias [C]
// out[b,c,l] = w0*x[l-1] + w1*x[l] + w2*x[l+1] + bias   (zero pad)
//
// HBM-streaming kernel, shuffle-halo variant (re-run: R6 was an infra failure):
//  - one block per 2048-element chunk of a row (chunks never cross rows)
//  - 2 float4 groups per thread, warp-coalesced LDG.128/STG.128
//  - halo neighbors via __shfl (register exchange), only lanes 0/31 issue a
//    predicated 1-lane scalar load for the warp-boundary element
//  - streaming store hint (__stcs): output is never re-read

#define CONV_L     8192
#define CONV_C     128
#define CONV_TPB   256
#define CONV_CHUNK 2048                          // elements per block
#define CONV_ITER  (CONV_CHUNK / 4 / CONV_TPB)   // 2 float4 groups per thread

__global__ void __launch_bounds__(CONV_TPB)
DepthWiseConv1d_23364622090654_kernel(const float* __restrict__ x,
                                      const float* __restrict__ w,
                                      const float* __restrict__ b,
                                      float* __restrict__ out)
{
    const size_t base = (size_t)blockIdx.x * CONV_CHUNK;
    const int c = (int)((base >> 13) & (CONV_C - 1));   // channel of this row

    const float w0   = __ldg(&w[c * 3 + 0]);
    const float w1   = __ldg(&w[c * 3 + 1]);
    const float w2   = __ldg(&w[c * 3 + 2]);
    const float bias = __ldg(&b[c]);

    const int t    = threadIdx.x;
    const int lane = t & 31;

    float4 v[CONV_ITER];
    float  lft[CONV_ITER], rgt[CONV_ITER];

    #pragma unroll
    for (int k = 0; k < CONV_ITER; k++) {
        const size_t gp = base + (size_t)(t + k * CONV_TPB) * 4;   // warp-coalesced
        v[k] = *reinterpret_cast<const float4*>(x + gp);

        // Warp-internal halo exchange: x[gp-1] = prev lane's v.w,
        //                              x[gp+4] = next lane's v.x.
        float l = __shfl_up_sync(0xFFFFFFFFu, v[k].w, 1);
        float r = __shfl_down_sync(0xFFFFFFFFu, v[k].x, 1);

        // Warp-boundary lanes fetch the single element outside the warp's
        // 512B window (L1/L2 hit); row edges are zero-padded.
        if (lane == 0) {
            const int pos = (int)(gp & (CONV_L - 1));
            l = (pos == 0) ? 0.0f : __ldg(x + gp - 1);
        }
        if (lane == 31) {
            const int pos = (int)(gp & (CONV_L - 1));
            r = (pos + 4 == CONV_L) ? 0.0f : __ldg(x + gp + 4);
        }
        lft[k] = l;
        rgt[k] = r;
    }

    #pragma unroll
    for (int k = 0; k < CONV_ITER; k++) {
        const size_t gp = base + (size_t)(t + k * CONV_TPB) * 4;
        float4 o;
        o.x = fmaf(w0, lft[k],  fmaf(w1, v[k].x, fmaf(w2, v[k].y, bias)));
        o.y = fmaf(w0, v[k].x,  fmaf(w1, v[k].y, fmaf(w2, v[k].z, bias)));
        o.z = fmaf(w0, v[k].y,  fmaf(w1, v[k].z, fmaf(w2, v[k].w, bias)));
        o.w = fmaf(w0, v[k].z,  fmaf(w1, v[k].w, fmaf(w2, rgt[k], bias)));
        __stcs(reinterpret_cast<float4*>(out + gp), o);   // streaming store
    }
}

extern "C" void kernel_launch(void* const* d_in, const int* in_sizes, int n_in,
                              void* d_out, int out_size)
{
    const float* x = (const float*)d_in[0];   // inputs  [B,C,L]
    const float* w = (const float*)d_in[1];   // weight  [C,3]
    const float* b = (const float*)d_in[2];   // bias    [C]
    float* out = (float*)d_out;

    const int rows   = in_sizes[0] / CONV_L;              // B*C = 4096
    const int blocks = rows * (CONV_L / CONV_CHUNK);      // 16384

    DepthWiseConv1d_23364622090654_kernel<<<blocks, CONV_TPB>>>(x, w, b, out);
}